// round 16
// baseline (speedup 1.0000x reference)
#include <cuda_runtime.h>
#include <math.h>

// ---- problem dims (fixed) ----
#define B_    4
#define T_    20
#define N_    256
#define L_    (T_*N_)    // 5120
#define P_    (B_*L_)    // 20480
#define CMAP_ 2048
#define NPSTR 10         // partial slots per query (parts <= 10)
#define KSLOT (P_/64)    // 320 per-block keysum slots

typedef unsigned long long ull;

// ---- device scratch ----
__device__ float g_cm4 [8*B_*256*4];           // 8 c-parts
__device__ float g_abc [P_*4];
__device__ float g_xr  [P_*2];
__device__ float g_part[(size_t)P_*NPSTR*4];   // query-major [query][part<=10] float4
__device__ float g_Sp  [KSLOT*2];
__device__ int   g_cnt [80];                    // per-group arrival counters (self-resetting)

// ---- helpers ----
__device__ __forceinline__ ull f2pack(float a, float b){ ull r; asm("mov.b64 %0,{%1,%2};":"=l"(r):"f"(a),"f"(b)); return r; }
__device__ __forceinline__ void f2unpack(ull v, float&a, float&b){ asm("mov.b64 {%0,%1},%2;":"=f"(a),"=f"(b):"l"(v)); }
__device__ __forceinline__ ull f2fma(ull a, ull b, ull c){ ull d; asm("fma.rn.f32x2 %0,%1,%2,%3;":"=l"(d):"l"(a),"l"(b),"l"(c)); return d; }
__device__ __forceinline__ ull f2add(ull a, ull b){ ull d; asm("add.rn.f32x2 %0,%1,%2;":"=l"(d):"l"(a),"l"(b)); return d; }
__device__ __forceinline__ float ftanh(float x){ float r; asm("tanh.approx.f32 %0,%1;":"=f"(r):"f"(x)); return r; }
__device__ __forceinline__ float fsig(float x){ return fmaf(0.5f, ftanh(0.5f*x), 0.5f); }

// ============================================================
// Kernel 1: compressor + folded vf projection — 256 blocks (8-way c-split)
// ============================================================
__global__ void __launch_bounds__(256) k_compress(
    const float* __restrict__ md, const float* __restrict__ cw, const float* __restrict__ cb,
    const float* __restrict__ vf_w)
{
    __shared__ float wT[256][36];
    __shared__ float cm32[32][33];

    const int cpart = blockIdx.x & 7;
    const int tile  = (blockIdx.x >> 3) & 7;
    const int b     = blockIdx.x >> 6;
    const int tid  = threadIdx.x;
    const int lane = tid & 31;
    const int warp = tid >> 5;
    const int hw   = tile*32 + lane;

    ull acc[16];
    #pragma unroll
    for (int i=0;i<16;i++) acc[i] = 0ULL;

    const int cb0 = cpart*256;
    #pragma unroll 4
    for (int r = 0; r < 32; r++)
        wT[tid][r] = cw[r*CMAP_ + cb0 + tid];
    __syncthreads();

    const int cl0 = warp*32;
    #pragma unroll 4
    for (int k = 0; k < 32; k++) {
        const int cl = cl0 + k;
        float m = md[(size_t)(b*CMAP_ + cb0 + cl)*256 + hw];
        ull m2 = f2pack(m, m);
        const ulonglong2* wrow = (const ulonglong2*)(&wT[cl][0]);
        #pragma unroll
        for (int i = 0; i < 8; i++) {
            ulonglong2 wv = wrow[i];
            acc[2*i]   = f2fma(m2, wv.x, acc[2*i]);
            acc[2*i+1] = f2fma(m2, wv.y, acc[2*i+1]);
        }
    }

    __syncthreads();
    {
        ull* row = (ull*)&wT[tid][0];
        #pragma unroll
        for (int i = 0; i < 16; i++) row[i] = acc[i];
    }
    __syncthreads();

    const int hwl = tid & 31;
    const int og  = tid >> 5;
    float r0=0.f, r1=0.f, r2=0.f, r3=0.f;
    #pragma unroll
    for (int w2 = 0; w2 < 8; w2++) {
        const float* rr = &wT[w2*32 + hwl][og*4];
        r0 += rr[0]; r1 += rr[1]; r2 += rr[2]; r3 += rr[3];
    }
    if (cpart == 0) {
        r0 += cb[og*4+0]; r1 += cb[og*4+1]; r2 += cb[og*4+2]; r3 += cb[og*4+3];
    }
    cm32[hwl][og*4+0] = r0; cm32[hwl][og*4+1] = r1;
    cm32[hwl][og*4+2] = r2; cm32[hwl][og*4+3] = r3;
    __syncthreads();

    if (og < 4) {
        float s = 0.f;
        #pragma unroll
        for (int j = 0; j < 32; j++)
            s = fmaf(vf_w[og*36 + 4 + j], cm32[hwl][j], s);
        g_cm4[(((size_t)cpart*B_ + b)*256 + tile*32 + hwl)*4 + og] = s;
    }
}

// ============================================================
// Kernel 2: per-point prep — 320 blocks x 64 threads, fast transcendentals
// ============================================================
__global__ void __launch_bounds__(64) k_points(
    const float* __restrict__ x,
    const float* __restrict__ w_ih, const float* __restrict__ b_ih, const float* __restrict__ b_hh,
    const float* __restrict__ vf_w, const float* __restrict__ vf_b,
    const float* __restrict__ fc_w, const float* __restrict__ fc_b,
    const float* __restrict__ fc2_w, const float* __restrict__ fc2_b)
{
    __shared__ float w0s[2], w1s[2];

    const int tid = threadIdx.x;
    const int p = blockIdx.x*64 + tid;
    const int b = p / L_;
    const int l = p % L_;
    const int t = l / N_;
    const int n = l % N_;

    const float x0 = x[((b*2+0)*T_ + t)*N_ + n];
    const float x1 = x[((b*2+1)*T_ + t)*N_ + n];
    const float ft = (float)t;
    const float xr0 = x0 + __sinf(ft);
    const float xr1 = x1 + __cosf(ft);

    float X[4];
    #pragma unroll
    for (int j = 0; j < 4; j++) {
        float ig = fmaf(w_ih[2*j],      xr0, fmaf(w_ih[2*j+1],      xr1, b_ih[j]    + b_hh[j]));
        float gg = fmaf(w_ih[2*(8+j)],  xr0, fmaf(w_ih[2*(8+j)+1],  xr1, b_ih[8+j]  + b_hh[8+j]));
        float og = fmaf(w_ih[2*(12+j)], xr0, fmaf(w_ih[2*(12+j)+1], xr1, b_ih[12+j] + b_hh[12+j]));
        float c  = fsig(ig)*ftanh(gg);
        X[j] = fsig(og)*ftanh(c);
    }

    const float ix = x0*(1.f/32.f) - 0.5f;
    const float iy = x1*(1.f/32.f) - 0.5f;
    const float x0f = floorf(ix), y0f = floorf(iy);
    const float wx1 = ix - x0f, wx0 = 1.f - wx1;
    const float wy1 = iy - y0f, wy0 = 1.f - wy1;
    const int xi0 = (int)x0f, yi0 = (int)y0f;

    float lcp0=0.f, lcp1=0.f, lcp2=0.f, lcp3=0.f;
    #pragma unroll
    for (int cy = 0; cy < 2; cy++) {
        #pragma unroll
        for (int cx = 0; cx < 2; cx++) {
            const int xi = xi0 + cx, yi = yi0 + cy;
            const float wgt = (cx ? wx1 : wx0) * (cy ? wy1 : wy0);
            if (xi >= 0 && xi < 16 && yi >= 0 && yi < 16) {
                #pragma unroll
                for (int part = 0; part < 8; part++) {
                    float4 v = *(const float4*)&g_cm4[(((size_t)part*B_ + b)*256 + yi*16 + xi)*4];
                    lcp0 = fmaf(wgt, v.x, lcp0);
                    lcp1 = fmaf(wgt, v.y, lcp1);
                    lcp2 = fmaf(wgt, v.z, lcp2);
                    lcp3 = fmaf(wgt, v.w, lcp3);
                }
            }
        }
    }

    float X2[4];
    {
        float lcp[4] = {lcp0, lcp1, lcp2, lcp3};
        #pragma unroll
        for (int i = 0; i < 4; i++) {
            float s = vf_b[i] + lcp[i];
            #pragma unroll
            for (int j = 0; j < 4; j++) s = fmaf(vf_w[i*36+j], X[j], s);
            X2[i] = s;
        }
    }

    float alpha = 0.f, beta = 0.f, gamma = 0.f;
    #pragma unroll
    for (int k = 0; k < 8; k++) {
        float q = fc_b[k];
        #pragma unroll
        for (int i = 0; i < 4; i++) q = fmaf(fc_w[k*4+i], X2[i], q);
        alpha = fmaf(q, fc2_b[k],    alpha);
        beta  = fmaf(q, fc2_w[2*k],  beta);
        gamma = fmaf(q, fc2_w[2*k+1],gamma);
    }
    float4 abc; abc.x = alpha*0.5f; abc.y = beta*0.5f; abc.z = gamma*0.5f; abc.w = 0.f;
    *(float4*)&g_abc[(size_t)p*4] = abc;
    float2 xr; xr.x = xr0; xr.y = xr1;
    *(float2*)&g_xr[(size_t)p*2] = xr;

    float s0 = xr0, s1 = xr1;
    #pragma unroll
    for (int off = 16; off > 0; off >>= 1) {
        s0 += __shfl_xor_sync(0xffffffffu, s0, off);
        s1 += __shfl_xor_sync(0xffffffffu, s1, off);
    }
    if ((tid & 31) == 0) { w0s[tid>>5] = s0; w1s[tid>>5] = s1; }
    __syncthreads();
    if (tid == 0) {
        g_Sp[blockIdx.x*2]     = w0s[0] + w0s[1];
        g_Sp[blockIdx.x*2 + 1] = w1s[0] + w1s[1];
    }
}

// ============================================================
// Kernel 3: attention + fused combine (last-block-finishes)
// 740 blocks = 148 x 5; 80 query-groups of 256; 10/9 parts per group
// ============================================================
__global__ void __launch_bounds__(256, 5) k_attn(
    const float* __restrict__ fc3_w, const float* __restrict__ fc3_b,
    const float* __restrict__ fco_w, const float* __restrict__ fco_b,
    float* __restrict__ out)
{
    __shared__ float4 sxr[285];   // up to 285 key pairs
    __shared__ int   sIsLast;
    __shared__ float sS0, sS1;

    const int bx = blockIdx.x;
    int g, j, P;
    if (bx < 200) { g = bx / 10;      j = bx - g*10;       P = 10; }
    else          { int r = bx - 200; g = 20 + r/9;        j = r - (g-20)*9; P = 9; }

    const int b  = g / 20;
    const int q0 = g*256 + threadIdx.x;
    const int ps = (2560*j)     / P;
    const int pe = (2560*(j+1)) / P;
    const int mh = pe - ps;

    for (int i = threadIdx.x; i < mh; i += 256) {
        float4 v = ((const float4*)g_xr)[((size_t)b*L_ >> 1) + ps + i];
        sxr[i] = make_float4(v.x, v.z, v.y, v.w);
    }

    ull al2, be2, ga2;
    {
        float4 abc = *(const float4*)&g_abc[(size_t)q0*4];
        al2 = f2pack(abc.x, abc.x);
        be2 = f2pack(abc.y, abc.y);
        ga2 = f2pack(abc.z, abc.z);
    }
    __syncthreads();

    ull u0 = 0ULL, u1 = 0ULL, u2 = 0ULL;
    const ulonglong2* kvp = (const ulonglong2*)sxr;

    #pragma unroll 4
    for (int m = 0; m < mh; m++) {
        ulonglong2 xv = kvp[m];
        ull z2 = f2fma(be2, xv.x, f2fma(ga2, xv.y, al2));
        float za, zb; f2unpack(z2, za, zb);
        float ta = ftanh(za);
        float tb = ftanh(zb);
        ull tp = f2pack(ta, tb);
        u0 = f2add(u0, tp);
        u1 = f2fma(tp, xv.x, u1);
        u2 = f2fma(tp, xv.y, u2);
    }

    {
        float a, bb, c, d, e, f;
        f2unpack(u0, a, bb);
        f2unpack(u1, c, d);
        f2unpack(u2, e, f);
        float4 w; w.x = a + bb; w.y = c + d; w.z = e + f; w.w = 0.f;
        *(float4*)&g_part[((size_t)q0*NPSTR + j)*4] = w;
    }

    // ---- last-block-finishes combine ----
    __threadfence();
    if (threadIdx.x == 0) {
        int old = atomicAdd(&g_cnt[g], 1);
        sIsLast = (old == P - 1);
        if (sIsLast) g_cnt[g] = 0;      // self-reset for graph replay
    }
    __syncthreads();
    if (!sIsLast) return;

    // warp 0: per-batch keysum S (80 slices, fixed order within lanes + shfl tree)
    if (threadIdx.x < 32) {
        float s0 = 0.f, s1 = 0.f;
        for (int s = threadIdx.x; s < 80; s += 32) {
            s0 += g_Sp[(b*80 + s)*2];
            s1 += g_Sp[(b*80 + s)*2 + 1];
        }
        #pragma unroll
        for (int off = 16; off > 0; off >>= 1) {
            s0 += __shfl_xor_sync(0xffffffffu, s0, off);
            s1 += __shfl_xor_sync(0xffffffffu, s1, off);
        }
        if (threadIdx.x == 0) { sS0 = s0; sS1 = s1; }
    }
    __syncthreads();

    // per-thread: combine P partials (L2-coherent loads, fixed order) + epilogue
    float v0 = 0.f, v1 = 0.f, v2 = 0.f;
    const float4* base = (const float4*)&g_part[(size_t)q0*NPSTR*4];
    for (int s = 0; s < P; s++) {
        float4 a = __ldcg(&base[s]);
        v0 += a.x; v1 += a.y; v2 += a.z;
    }

    const float t0 = 0.5f*(v0 + (float)L_);
    const float t1 = 0.5f*(v1 + sS0);
    const float t2 = 0.5f*(v2 + sS1);

    float r0 = fco_b[0], r1 = fco_b[1];
    #pragma unroll
    for (int i = 0; i < 8; i++) {
        float o = fmaf(t0, fc3_b[i], fmaf(t1, fc3_w[2*i], t2*fc3_w[2*i+1]));
        o = (o > 0.5f) ? o : 0.f;
        r0 = fmaf(fco_w[i],   o, r0);
        r1 = fmaf(fco_w[8+i], o, r1);
    }
    const int l = q0 % L_;
    const int t = l / N_;
    const int n = l % N_;
    out[((b*2+0)*T_ + t)*N_ + n] = r0;
    out[((b*2+1)*T_ + t)*N_ + n] = r1;
}

// ============================================================
extern "C" void kernel_launch(void* const* d_in, const int* in_sizes, int n_in,
                              void* d_out, int out_size)
{
    const float* x      = (const float*)d_in[0];
    const float* md     = (const float*)d_in[1];
    const float* w_ih   = (const float*)d_in[2];
    const float* b_ih   = (const float*)d_in[3];
    const float* b_hh   = (const float*)d_in[4];
    const float* comp_w = (const float*)d_in[5];
    const float* comp_b = (const float*)d_in[6];
    const float* vf_w   = (const float*)d_in[7];
    const float* vf_b   = (const float*)d_in[8];
    const float* fc_w   = (const float*)d_in[9];
    const float* fc_b   = (const float*)d_in[10];
    const float* fc2_w  = (const float*)d_in[11];
    const float* fc2_b  = (const float*)d_in[12];
    const float* fc3_w  = (const float*)d_in[13];
    const float* fc3_b  = (const float*)d_in[14];
    const float* fco_w  = (const float*)d_in[15];
    const float* fco_b  = (const float*)d_in[16];
    float* out = (float*)d_out;

    k_compress<<<256, 256>>>(md, comp_w, comp_b, vf_w);
    k_points<<<P_/64, 64>>>(x, w_ih, b_ih, b_hh, vf_w, vf_b,
                            fc_w, fc_b, fc2_w, fc2_b);
    k_attn<<<740, 256>>>(fc3_w, fc3_b, fco_w, fco_b, out);
}

// round 17
// speedup vs baseline: 1.5848x; 1.5848x over previous
#include <cuda_runtime.h>
#include <math.h>

// ---- problem dims (fixed) ----
#define B_    4
#define T_    20
#define N_    256
#define L_    (T_*N_)    // 5120
#define P_    (B_*T_*N_) // 20480
#define CMAP_ 2048
#define NPSTR 10         // partial slots per query (parts <= 10)
#define KSLOT (P_/256)   // 80 per-block keysum slots

typedef unsigned long long ull;

// ---- device scratch ----
__device__ float g_cm4 [8*B_*256*4];           // 8 c-parts
__device__ float g_abc [P_*4];
__device__ float g_xr  [P_*2];
__device__ float g_part[(size_t)P_*NPSTR*4];   // query-major [query][part<=10] float4
__device__ float g_Sp  [KSLOT*2];

// ---- helpers ----
__device__ __forceinline__ ull f2pack(float a, float b){ ull r; asm("mov.b64 %0,{%1,%2};":"=l"(r):"f"(a),"f"(b)); return r; }
__device__ __forceinline__ void f2unpack(ull v, float&a, float&b){ asm("mov.b64 {%0,%1},%2;":"=f"(a),"=f"(b):"l"(v)); }
__device__ __forceinline__ ull f2fma(ull a, ull b, ull c){ ull d; asm("fma.rn.f32x2 %0,%1,%2,%3;":"=l"(d):"l"(a),"l"(b),"l"(c)); return d; }
__device__ __forceinline__ ull f2add(ull a, ull b){ ull d; asm("add.rn.f32x2 %0,%1,%2;":"=l"(d):"l"(a),"l"(b)); return d; }
__device__ __forceinline__ float ftanh(float x){ float r; asm("tanh.approx.f32 %0,%1;":"=f"(r):"f"(x)); return r; }
__device__ __forceinline__ float fsig(float x){ return fmaf(0.5f, ftanh(0.5f*x), 0.5f); }

// ============================================================
// Kernel 1: compressor + folded vf projection — 256 blocks (8-way c-split)
// ============================================================
__global__ void __launch_bounds__(256) k_compress(
    const float* __restrict__ md, const float* __restrict__ cw, const float* __restrict__ cb,
    const float* __restrict__ vf_w)
{
    __shared__ float wT[256][36];
    __shared__ float cm32[32][33];

    const int cpart = blockIdx.x & 7;            // 8 c-parts of 256 channels
    const int tile  = (blockIdx.x >> 3) & 7;
    const int b     = blockIdx.x >> 6;
    const int tid  = threadIdx.x;
    const int lane = tid & 31;
    const int warp = tid >> 5;
    const int hw   = tile*32 + lane;

    ull acc[16];
    #pragma unroll
    for (int i=0;i<16;i++) acc[i] = 0ULL;

    const int cb0 = cpart*256;
    #pragma unroll 4
    for (int r = 0; r < 32; r++)
        wT[tid][r] = cw[r*CMAP_ + cb0 + tid];
    __syncthreads();

    const int cl0 = warp*32;
    #pragma unroll 4
    for (int k = 0; k < 32; k++) {
        const int cl = cl0 + k;
        float m = md[(size_t)(b*CMAP_ + cb0 + cl)*256 + hw];
        ull m2 = f2pack(m, m);
        const ulonglong2* wrow = (const ulonglong2*)(&wT[cl][0]);
        #pragma unroll
        for (int i = 0; i < 8; i++) {
            ulonglong2 wv = wrow[i];
            acc[2*i]   = f2fma(m2, wv.x, acc[2*i]);
            acc[2*i+1] = f2fma(m2, wv.y, acc[2*i+1]);
        }
    }

    __syncthreads();
    {
        ull* row = (ull*)&wT[tid][0];
        #pragma unroll
        for (int i = 0; i < 16; i++) row[i] = acc[i];
    }
    __syncthreads();

    const int hwl = tid & 31;
    const int og  = tid >> 5;
    float r0=0.f, r1=0.f, r2=0.f, r3=0.f;
    #pragma unroll
    for (int w2 = 0; w2 < 8; w2++) {
        const float* rr = &wT[w2*32 + hwl][og*4];
        r0 += rr[0]; r1 += rr[1]; r2 += rr[2]; r3 += rr[3];
    }
    if (cpart == 0) {
        r0 += cb[og*4+0]; r1 += cb[og*4+1]; r2 += cb[og*4+2]; r3 += cb[og*4+3];
    }
    cm32[hwl][og*4+0] = r0; cm32[hwl][og*4+1] = r1;
    cm32[hwl][og*4+2] = r2; cm32[hwl][og*4+3] = r3;
    __syncthreads();

    if (og < 4) {
        float s = 0.f;
        #pragma unroll
        for (int j = 0; j < 32; j++)
            s = fmaf(vf_w[og*36 + 4 + j], cm32[hwl][j], s);
        g_cm4[(((size_t)cpart*B_ + b)*256 + tile*32 + hwl)*4 + og] = s;
    }
}

// ============================================================
// Kernel 2: per-point prep — 80 blocks x 256 threads, fast transcendentals
// ============================================================
__global__ void __launch_bounds__(256) k_points(
    const float* __restrict__ x,
    const float* __restrict__ w_ih, const float* __restrict__ b_ih, const float* __restrict__ b_hh,
    const float* __restrict__ vf_w, const float* __restrict__ vf_b,
    const float* __restrict__ fc_w, const float* __restrict__ fc_b,
    const float* __restrict__ fc2_w, const float* __restrict__ fc2_b)
{
    __shared__ float r0s[256], r1s[256];

    const int tid = threadIdx.x;
    const int p = blockIdx.x*256 + tid;
    const int b = p / L_;
    const int l = p % L_;
    const int t = l / N_;
    const int n = l % N_;

    const float x0 = x[((b*2+0)*T_ + t)*N_ + n];
    const float x1 = x[((b*2+1)*T_ + t)*N_ + n];
    const float ft = (float)t;
    const float xr0 = x0 + __sinf(ft);
    const float xr1 = x1 + __cosf(ft);

    // single-step LSTM with HW tanh approx
    float X[4];
    #pragma unroll
    for (int j = 0; j < 4; j++) {
        float ig = fmaf(w_ih[2*j],      xr0, fmaf(w_ih[2*j+1],      xr1, b_ih[j]    + b_hh[j]));
        float gg = fmaf(w_ih[2*(8+j)],  xr0, fmaf(w_ih[2*(8+j)+1],  xr1, b_ih[8+j]  + b_hh[8+j]));
        float og = fmaf(w_ih[2*(12+j)], xr0, fmaf(w_ih[2*(12+j)+1], xr1, b_ih[12+j] + b_hh[12+j]));
        float c  = fsig(ig)*ftanh(gg);
        X[j] = fsig(og)*ftanh(c);
    }

    const float ix = x0*(1.f/32.f) - 0.5f;
    const float iy = x1*(1.f/32.f) - 0.5f;
    const float x0f = floorf(ix), y0f = floorf(iy);
    const float wx1 = ix - x0f, wx0 = 1.f - wx1;
    const float wy1 = iy - y0f, wy0 = 1.f - wy1;
    const int xi0 = (int)x0f, yi0 = (int)y0f;

    float lcp0=0.f, lcp1=0.f, lcp2=0.f, lcp3=0.f;
    #pragma unroll
    for (int cy = 0; cy < 2; cy++) {
        #pragma unroll
        for (int cx = 0; cx < 2; cx++) {
            const int xi = xi0 + cx, yi = yi0 + cy;
            const float wgt = (cx ? wx1 : wx0) * (cy ? wy1 : wy0);
            if (xi >= 0 && xi < 16 && yi >= 0 && yi < 16) {
                #pragma unroll
                for (int part = 0; part < 8; part++) {
                    float4 v = *(const float4*)&g_cm4[(((size_t)part*B_ + b)*256 + yi*16 + xi)*4];
                    lcp0 = fmaf(wgt, v.x, lcp0);
                    lcp1 = fmaf(wgt, v.y, lcp1);
                    lcp2 = fmaf(wgt, v.z, lcp2);
                    lcp3 = fmaf(wgt, v.w, lcp3);
                }
            }
        }
    }

    float X2[4];
    {
        float lcp[4] = {lcp0, lcp1, lcp2, lcp3};
        #pragma unroll
        for (int i = 0; i < 4; i++) {
            float s = vf_b[i] + lcp[i];
            #pragma unroll
            for (int j = 0; j < 4; j++) s = fmaf(vf_w[i*36+j], X[j], s);
            X2[i] = s;
        }
    }

    float alpha = 0.f, beta = 0.f, gamma = 0.f;
    #pragma unroll
    for (int k = 0; k < 8; k++) {
        float q = fc_b[k];
        #pragma unroll
        for (int i = 0; i < 4; i++) q = fmaf(fc_w[k*4+i], X2[i], q);
        alpha = fmaf(q, fc2_b[k],    alpha);
        beta  = fmaf(q, fc2_w[2*k],  beta);
        gamma = fmaf(q, fc2_w[2*k+1],gamma);
    }
    float4 abc; abc.x = alpha*0.5f; abc.y = beta*0.5f; abc.z = gamma*0.5f; abc.w = 0.f;
    *(float4*)&g_abc[(size_t)p*4] = abc;
    float2 xr; xr.x = xr0; xr.y = xr1;
    *(float2*)&g_xr[(size_t)p*2] = xr;

    // per-block keysum partial (deterministic tree), 80 slots
    r0s[tid] = xr0; r1s[tid] = xr1;
    __syncthreads();
    #pragma unroll
    for (int off = 128; off > 0; off >>= 1) {
        if (tid < off) { r0s[tid] += r0s[tid+off]; r1s[tid] += r1s[tid+off]; }
        __syncthreads();
    }
    if (tid == 0) {
        g_Sp[blockIdx.x*2]     = r0s[0];
        g_Sp[blockIdx.x*2 + 1] = r1s[0];
    }
}

// ============================================================
// Kernel 3: attention partials — 740 blocks = 148 x 5, 1 query/thread
// 80 query-groups of 256; groups 0-19: 10 parts, groups 20-79: 9 parts
// ============================================================
__global__ void __launch_bounds__(256, 5) k_attn()
{
    __shared__ float4 sxr[285];   // up to 285 key pairs (570 keys)

    const int bx = blockIdx.x;
    int g, j, P;
    if (bx < 200) { g = bx / 10;      j = bx - g*10;       P = 10; }
    else          { int r = bx - 200; g = 20 + r/9;        j = r - (g-20)*9; P = 9; }

    const int b  = g / 20;
    const int q0 = g*256 + threadIdx.x;
    const int ps = (2560*j)     / P;
    const int pe = (2560*(j+1)) / P;
    const int mh = pe - ps;

    for (int i = threadIdx.x; i < mh; i += 256) {
        float4 v = ((const float4*)g_xr)[((size_t)b*L_ >> 1) + ps + i];
        sxr[i] = make_float4(v.x, v.z, v.y, v.w);
    }

    ull al2, be2, ga2;
    {
        float4 abc = *(const float4*)&g_abc[(size_t)q0*4];
        al2 = f2pack(abc.x, abc.x);
        be2 = f2pack(abc.y, abc.y);
        ga2 = f2pack(abc.z, abc.z);
    }
    __syncthreads();

    ull u0 = 0ULL, u1 = 0ULL, u2 = 0ULL;
    const ulonglong2* kvp = (const ulonglong2*)sxr;

    #pragma unroll 4
    for (int m = 0; m < mh; m++) {
        ulonglong2 xv = kvp[m];
        ull z2 = f2fma(be2, xv.x, f2fma(ga2, xv.y, al2));
        float za, zb; f2unpack(z2, za, zb);
        float ta = ftanh(za);
        float tb = ftanh(zb);
        ull tp = f2pack(ta, tb);
        u0 = f2add(u0, tp);
        u1 = f2fma(tp, xv.x, u1);
        u2 = f2fma(tp, xv.y, u2);
    }

    float a, bb, c, d, e, f;
    f2unpack(u0, a, bb);
    f2unpack(u1, c, d);
    f2unpack(u2, e, f);
    float4 w; w.x = a + bb; w.y = c + d; w.z = e + f; w.w = 0.f;
    *(float4*)&g_part[((size_t)q0*NPSTR + j)*4] = w;
}

// ============================================================
// Kernel 4: combine (<=10 parts) + sigmoid restore + rank-3 V + threshold + fco
// ============================================================
__global__ void __launch_bounds__(256) k_combine(
    const float* __restrict__ fc3_w, const float* __restrict__ fc3_b,
    const float* __restrict__ fco_w, const float* __restrict__ fco_b,
    float* __restrict__ out)
{
    const int idx = blockIdx.x*256 + threadIdx.x;
    const int p   = idx >> 2;
    const int sub = idx & 3;

    const int g = p >> 8;
    const int P = (g < 20) ? 10 : 9;

    const float4* base = (const float4*)&g_part[(size_t)p*NPSTR*4];

    float u0=0.f, u1=0.f, u2=0.f;
    #pragma unroll
    for (int i = 0; i < 3; i++) {
        const int s = sub + i*4;
        if (s < P) {
            float4 a = base[s];
            u0 += a.x; u1 += a.y; u2 += a.z;
        }
    }
    u0 += __shfl_xor_sync(0xffffffffu, u0, 1);
    u1 += __shfl_xor_sync(0xffffffffu, u1, 1);
    u2 += __shfl_xor_sync(0xffffffffu, u2, 1);
    u0 += __shfl_xor_sync(0xffffffffu, u0, 2);
    u1 += __shfl_xor_sync(0xffffffffu, u1, 2);
    u2 += __shfl_xor_sync(0xffffffffu, u2, 2);

    if (sub == 0) {
        const int b = p / L_;
        float S0 = 0.f, S1 = 0.f;
        #pragma unroll
        for (int s = 0; s < 20; s++) {   // 20 keysum slots per batch
            S0 += g_Sp[(b*20 + s)*2];
            S1 += g_Sp[(b*20 + s)*2 + 1];
        }
        const float t0 = 0.5f*(u0 + (float)L_);
        const float t1 = 0.5f*(u1 + S0);
        const float t2 = 0.5f*(u2 + S1);

        float r0 = fco_b[0], r1 = fco_b[1];
        #pragma unroll
        for (int i = 0; i < 8; i++) {
            float o = fmaf(t0, fc3_b[i], fmaf(t1, fc3_w[2*i], t2*fc3_w[2*i+1]));
            o = (o > 0.5f) ? o : 0.f;
            r0 = fmaf(fco_w[i],   o, r0);
            r1 = fmaf(fco_w[8+i], o, r1);
        }
        const int l = p % L_;
        const int t = l / N_;
        const int n = l % N_;
        out[((b*2+0)*T_ + t)*N_ + n] = r0;
        out[((b*2+1)*T_ + t)*N_ + n] = r1;
    }
}

// ============================================================
extern "C" void kernel_launch(void* const* d_in, const int* in_sizes, int n_in,
                              void* d_out, int out_size)
{
    const float* x      = (const float*)d_in[0];
    const float* md     = (const float*)d_in[1];
    const float* w_ih   = (const float*)d_in[2];
    const float* b_ih   = (const float*)d_in[3];
    const float* b_hh   = (const float*)d_in[4];
    const float* comp_w = (const float*)d_in[5];
    const float* comp_b = (const float*)d_in[6];
    const float* vf_w   = (const float*)d_in[7];
    const float* vf_b   = (const float*)d_in[8];
    const float* fc_w   = (const float*)d_in[9];
    const float* fc_b   = (const float*)d_in[10];
    const float* fc2_w  = (const float*)d_in[11];
    const float* fc2_b  = (const float*)d_in[12];
    const float* fc3_w  = (const float*)d_in[13];
    const float* fc3_b  = (const float*)d_in[14];
    const float* fco_w  = (const float*)d_in[15];
    const float* fco_b  = (const float*)d_in[16];
    float* out = (float*)d_out;

    k_compress<<<256, 256>>>(md, comp_w, comp_b, vf_w);
    k_points<<<P_/256, 256>>>(x, w_ih, b_ih, b_hh, vf_w, vf_b,
                              fc_w, fc_b, fc2_w, fc2_b);
    k_attn<<<740, 256>>>();
    k_combine<<<(P_*4)/256, 256>>>(fc3_w, fc3_b, fco_w, fco_b, out);
}